// round 13
// baseline (speedup 1.0000x reference)
#include <cuda_runtime.h>

// CapsuleLayer collapse: routing softmax over a singleton axis is identically 1,
// so out = squash( s ),  s[b,j,k] = sum_{i,u} W[i,j,k,u] * x[b,u,i].
// GEMM: C[32 x 1024] = A[32 x 32768] * B[32768 x 1024], K = (i,u).
//
// M = 32 lives entirely in ONE thread's accumulators as 16 f32x2 b-pairs:
// each W element is smem-read by exactly one thread, x reads are warp-broadcast.
// R8 fix: 16B-granule swizzle of the W smem layout. The verbatim layout gave
// lane stride 64B => 16-way LDS bank conflicts; swizzled layout hits the
// 4-cycle crossbar floor.

#define N_B    32
#define N_IU   16
#define N_IC   2048
#define N_N    1024
#define IC_PER 16              // i's per GEMM block (stages)
#define N_ICCH (N_IC / IC_PER) // 128 K-split chunks
#define S_STG  IC_PER

// Scratch (no allocation allowed)
__device__ float g_xT[N_IC * N_IU * N_B];        // [i][u][b]  4 MB
__device__ float g_part[N_ICCH][N_B][N_N];       // 16 MB K-split partials

typedef unsigned long long ull;

__device__ __forceinline__ ull fma2(ull a, ull b, ull c) {
    ull d;
    asm("fma.rn.f32x2 %0, %1, %2, %3;" : "=l"(d) : "l"(a), "l"(b), "l"(c));
    return d;
}
__device__ __forceinline__ ull dup2(float x) {
    ull d;
    asm("mov.b64 %0, {%1, %1};" : "=l"(d) : "f"(x));
    return d;
}
__device__ __forceinline__ unsigned su32(const void* p) {
    return (unsigned)__cvta_generic_to_shared(p);
}
__device__ __forceinline__ void cp16(unsigned dst, const void* src) {
    asm volatile("cp.async.cg.shared.global [%0], [%1], 16;" :: "r"(dst), "l"(src));
}

// ---------------------------------------------------------------------------
// Kernel 1: x[b][u][i] -> xT[i][u][b].
// grid (64 i-tiles of 32, 16 u) = 1024 blocks, block (32,8) = 256 thr.
// Coalesced reads along i, coalesced writes along b, conflict-free smem.
// ---------------------------------------------------------------------------
__global__ void __launch_bounds__(256) transpose_x_kernel(const float* __restrict__ x) {
    __shared__ float tile[32][33];
    const int i0 = blockIdx.x * 32;
    const int u  = blockIdx.y;
    const int tx = threadIdx.x, ty = threadIdx.y;

    #pragma unroll
    for (int k = 0; k < 4; k++) {
        const int b = ty + 8 * k;
        tile[b][tx] = x[(size_t)b * (N_IU * N_IC) + (size_t)u * N_IC + i0 + tx];
    }
    __syncthreads();
    #pragma unroll
    for (int k = 0; k < 4; k++) {
        const int row = ty + 8 * k;     // local i
        g_xT[(size_t)(i0 + row) * (N_IU * N_B) + u * N_B + tx] = tile[tx][row];
    }
}

// ---------------------------------------------------------------------------
// Kernel 2: K-split GEMM, b-pair-packed f32x2 FMAs, cp.async triple buffer.
// grid (128 ic, 4 jq), 128 threads, 4 CTAs/SM.
// Block tile: M=32 (all b, in-regs), N=256, K-chunk = 16 i * 16 u = 256.
// Thread: 2 n-columns (t and t+128), 16 b-pair accs each = 64 acc regs.
// W smem: row n holds its four 16B granules at slots (g + (n>>1)) & 3.
// ---------------------------------------------------------------------------
#define WS_F 4096                       // 256 n * 16 u floats per stage
#define XS_F 512                        // 16 u * 32 b floats per stage
#define GEMM_SMEM_BYTES ((3 * WS_F + 3 * XS_F) * 4)   // 55296 B

__global__ void __launch_bounds__(128, 4) gemm_part_kernel(const float* __restrict__ W) {
    extern __shared__ float sm[];
    float* Wsm = sm;                    // 3 stage buffers
    float* Xsm = sm + 3 * WS_F;

    const int t  = threadIdx.x;
    const int ic = blockIdx.x;
    const int jq = blockIdx.y;

    const float* Wbase = W    + (size_t)ic * IC_PER * 16384 + (size_t)jq * 4096;
    const float* Xbase = g_xT + (size_t)ic * IC_PER * (N_IU * N_B);

    ull acc0[16], acc1[16];
    #pragma unroll
    for (int p = 0; p < 16; p++) { acc0[p] = 0ULL; acc1[p] = 0ULL; }

    auto issue = [&](int s) {
        const int buf = s % 3;
        const float* wg = Wbase + (size_t)s * 16384;
        float* wd = Wsm + buf * WS_F;
        #pragma unroll
        for (int p = 0; p < 8; p++) {
            const int off  = p * 512 + t * 4;              // source float offset
            const int row  = off >> 4;                     // n row (16 floats each)
            const int slot = ((t & 3) + (row >> 1)) & 3;   // swizzled 16B granule
            cp16(su32(wd + (row << 4) + (slot << 2)), wg + off);
        }
        cp16(su32(Xsm + buf * XS_F + t * 4), Xbase + s * XS_F + t * 4);
        asm volatile("cp.async.commit_group;");
    };

    issue(0);
    issue(1);

    const int slotbase = (t >> 1) & 3;   // same for row t and row t+128

    #pragma unroll 1
    for (int s = 0; s < S_STG; s++) {
        if (s < S_STG - 1) asm volatile("cp.async.wait_group 1;");
        else               asm volatile("cp.async.wait_group 0;");
        __syncthreads();

        const int buf = s % 3;
        const float* WsB = Wsm + buf * WS_F;
        const float* XsB = Xsm + buf * XS_F;

        #pragma unroll
        for (int r4 = 0; r4 < 4; r4++) {
            const int sl = (r4 + slotbase) & 3;
            // this thread's two n-columns, 4 u's each (one conflict-free LDS.128 apiece)
            const float4 w0 = *reinterpret_cast<const float4*>(WsB + t * 16 + sl * 4);
            const float4 w1 = *reinterpret_cast<const float4*>(WsB + (t + 128) * 16 + sl * 4);
            const float wa0[4] = {w0.x, w0.y, w0.z, w0.w};
            const float wa1[4] = {w1.x, w1.y, w1.z, w1.w};
            #pragma unroll
            for (int q = 0; q < 4; q++) {
                const int r = r4 * 4 + q;                 // u index
                const ull wd0 = dup2(wa0[q]);
                const ull wd1 = dup2(wa1[q]);
                #pragma unroll
                for (int h = 0; h < 8; h++) {             // 4 b's per iter (broadcast LDS)
                    const ulonglong2 xv = *reinterpret_cast<const ulonglong2*>(XsB + r * 32 + h * 4);
                    acc0[2 * h]     = fma2(xv.x, wd0, acc0[2 * h]);
                    acc0[2 * h + 1] = fma2(xv.y, wd0, acc0[2 * h + 1]);
                    acc1[2 * h]     = fma2(xv.x, wd1, acc1[2 * h]);
                    acc1[2 * h + 1] = fma2(xv.y, wd1, acc1[2 * h + 1]);
                }
            }
        }
        if (s + 2 < S_STG) issue(s + 2);   // buf (s+2)%3 freed by this iter's barrier
    }

    // epilogue: deterministic partials, coalesced scalar rows (lanes span n)
    float* outp = &g_part[ic][0][jq * 256];
    #pragma unroll
    for (int bp = 0; bp < 16; bp++) {
        union { ull u; float2 f; } c0, c1;
        c0.u = acc0[bp]; c1.u = acc1[bp];
        outp[(size_t)(2 * bp)     * N_N + t]       = c0.f.x;
        outp[(size_t)(2 * bp + 1) * N_N + t]       = c0.f.y;
        outp[(size_t)(2 * bp)     * N_N + 128 + t] = c1.f.x;
        outp[(size_t)(2 * bp + 1) * N_N + 128 + t] = c1.f.y;
    }
}

// ---------------------------------------------------------------------------
// Kernel 3: sum 128 K-split partials + squash.
//   msq[b,k] = sum_j s[b,j,k]^2 ;  out = s * msq / ((1+msq) * sqrt(msq))
// grid (32 b, 4 k-quarters), block 256: t = j*16 + kl.
// ---------------------------------------------------------------------------
__global__ void reduce_squash_kernel(float* __restrict__ out) {
    __shared__ float smv[256];
    __shared__ float msq[16];
    const int b  = blockIdx.x;
    const int kq = blockIdx.y;
    const int t  = threadIdx.x;
    const int j  = t >> 4;
    const int kl = t & 15;
    const int n  = j * 64 + kq * 16 + kl;

    float s = 0.0f;
    #pragma unroll 16
    for (int ic = 0; ic < N_ICCH; ic++)
        s += g_part[ic][b][n];

    smv[t] = s;
    __syncthreads();
    if (t < 16) {
        float m = 0.0f;
        #pragma unroll
        for (int jj = 0; jj < 16; jj++) {
            const float v = smv[jj * 16 + t];
            m += v * v;
        }
        msq[t] = m;
    }
    __syncthreads();
    const float m = msq[kl];
    out[(size_t)b * N_N + n] = s * m / ((1.0f + m) * sqrtf(m));
}

// ---------------------------------------------------------------------------
extern "C" void kernel_launch(void* const* d_in, const int* in_sizes, int n_in,
                              void* d_out, int out_size) {
    const float* x = (const float*)d_in[0];
    const float* W = (const float*)d_in[1];
    if (n_in >= 2 && in_sizes[0] > in_sizes[1]) {   // safety: x is the smaller input
        x = (const float*)d_in[1];
        W = (const float*)d_in[0];
    }
    cudaFuncSetAttribute(gemm_part_kernel,
                         cudaFuncAttributeMaxDynamicSharedMemorySize, GEMM_SMEM_BYTES);
    transpose_x_kernel<<<dim3(N_IC / 32, N_IU), dim3(32, 8)>>>(x);
    gemm_part_kernel<<<dim3(N_ICCH, 4), 128, GEMM_SMEM_BYTES>>>(W);
    reduce_squash_kernel<<<dim3(N_B, 4), 256>>>((float*)d_out);
}